// round 1
// baseline (speedup 1.0000x reference)
#include <cuda_runtime.h>

// Problem dims (fixed by the dataset)
#define BATCH 8192
#define NDIM  4096   // input feature dim (K of the GEMM)
#define MDIM  4096   // output feature dim
#define NGRP  (MDIM * 512)   // total 8-element codebook groups in W

// ---------------------------------------------------------------------------
// Scratch (allocation-free: __device__ globals per harness rules)
// ---------------------------------------------------------------------------
__device__ float g_xrht[(size_t)BATCH * NDIM];   // 128 MB
__device__ float g_W   [(size_t)MDIM  * NDIM];   // 64 MB
__device__ float g_yrht[(size_t)BATCH * MDIM];   // 128 MB

// ---------------------------------------------------------------------------
// Kernel 1: x_rht = FHT(x * SV) / 64     (one block per row, smem butterfly)
// ---------------------------------------------------------------------------
__global__ __launch_bounds__(1024) void fht_pre_kernel(
    const float* __restrict__ x, const float* __restrict__ SV)
{
    __shared__ float s[NDIM];
    const int row = blockIdx.x;
    const int tid = threadIdx.x;
    const float* xr = x + (size_t)row * NDIM;

#pragma unroll
    for (int k = 0; k < 4; k++) {
        int i = tid + k * 1024;
        s[i] = xr[i] * SV[i];
    }

    for (int h = 1; h < NDIM; h <<= 1) {
        __syncthreads();
#pragma unroll
        for (int r = 0; r < 2; r++) {
            int p = tid + r * 1024;             // pair index 0..2047
            int i = ((p & ~(h - 1)) << 1) | (p & (h - 1));
            float a = s[i], b = s[i + h];
            s[i]     = a + b;
            s[i + h] = a - b;
        }
    }
    __syncthreads();

    float* o = g_xrht + (size_t)row * NDIM;
#pragma unroll
    for (int k = 0; k < 4; k++) {
        int i = tid + k * 1024;
        o[i] = s[i] * 0.015625f;               // 1/sqrt(4096)
    }
}

// ---------------------------------------------------------------------------
// Kernel 2: dequantize W:  W[g*8 + j] = cb[q][j] + irs * cb2[q2][j]
// ---------------------------------------------------------------------------
__global__ __launch_bounds__(256) void dequant_kernel(
    const int* __restrict__ Qidxs, const int* __restrict__ Qidxs2,
    const float* __restrict__ cb, const float* __restrict__ cb2,
    const float* __restrict__ irs_p)
{
    int g = blockIdx.x * blockDim.x + threadIdx.x;
    if (g >= NGRP) return;
    const float irs = __ldg(irs_p);
    const int q  = Qidxs[g];
    const int q2 = Qidxs2[g];

    float4 c0 = __ldg((const float4*)cb  + q  * 2);
    float4 c1 = __ldg((const float4*)cb  + q  * 2 + 1);
    float4 d0 = __ldg((const float4*)cb2 + q2 * 2);
    float4 d1 = __ldg((const float4*)cb2 + q2 * 2 + 1);

    float4 w0, w1;
    w0.x = fmaf(irs, d0.x, c0.x);  w0.y = fmaf(irs, d0.y, c0.y);
    w0.z = fmaf(irs, d0.z, c0.z);  w0.w = fmaf(irs, d0.w, c0.w);
    w1.x = fmaf(irs, d1.x, c1.x);  w1.y = fmaf(irs, d1.y, c1.y);
    w1.z = fmaf(irs, d1.z, c1.z);  w1.w = fmaf(irs, d1.w, c1.w);

    ((float4*)g_W)[(size_t)g * 2]     = w0;
    ((float4*)g_W)[(size_t)g * 2 + 1] = w1;
}

// ---------------------------------------------------------------------------
// Kernel 3: y_rht = x_rht @ W^T   (NT SGEMM: both operands K-contiguous)
// 128x128 block tile, BK=8, 8x8 per thread, 256 threads.
// ---------------------------------------------------------------------------
__global__ __launch_bounds__(256) void sgemm_kernel()
{
    __shared__ float As[8][128];
    __shared__ float Bs[8][128];

    const int tid = threadIdx.x;
    const int tx = tid & 15;        // 0..15  -> 8 output columns each
    const int ty = tid >> 4;        // 0..15  -> 8 output rows each

    const int brow = blockIdx.y * 128;   // batch-row tile
    const int bcol = blockIdx.x * 128;   // m-column tile

    // Cooperative load mapping: thread -> (row within tile, half of 8-wide K slab)
    const int lrow = tid >> 1;           // 0..127
    const int lcol = (tid & 1) * 4;      // 0 or 4

    const float* Aptr = g_xrht + (size_t)(brow + lrow) * NDIM + lcol;
    const float* Bptr = g_W    + (size_t)(bcol + lrow) * NDIM + lcol;

    float acc[8][8];
#pragma unroll
    for (int i = 0; i < 8; i++)
#pragma unroll
        for (int j = 0; j < 8; j++) acc[i][j] = 0.0f;

    for (int k0 = 0; k0 < NDIM; k0 += 8) {
        float4 a4 = *(const float4*)(Aptr + k0);
        float4 b4 = *(const float4*)(Bptr + k0);

        __syncthreads();   // previous iteration's compute done before overwrite
        As[lcol + 0][lrow] = a4.x;  As[lcol + 1][lrow] = a4.y;
        As[lcol + 2][lrow] = a4.z;  As[lcol + 3][lrow] = a4.w;
        Bs[lcol + 0][lrow] = b4.x;  Bs[lcol + 1][lrow] = b4.y;
        Bs[lcol + 2][lrow] = b4.z;  Bs[lcol + 3][lrow] = b4.w;
        __syncthreads();

#pragma unroll
        for (int k = 0; k < 8; k++) {
            float ra[8], rb[8];
#pragma unroll
            for (int i = 0; i < 8; i++) ra[i] = As[k][ty * 8 + i];
#pragma unroll
            for (int j = 0; j < 8; j++) rb[j] = Bs[k][tx * 8 + j];
#pragma unroll
            for (int i = 0; i < 8; i++)
#pragma unroll
                for (int j = 0; j < 8; j++)
                    acc[i][j] = fmaf(ra[i], rb[j], acc[i][j]);
        }
    }

#pragma unroll
    for (int i = 0; i < 8; i++) {
        float* crow = g_yrht + (size_t)(brow + ty * 8 + i) * MDIM + bcol + tx * 8;
        *(float4*)(crow)     = make_float4(acc[i][0], acc[i][1], acc[i][2], acc[i][3]);
        *(float4*)(crow + 4) = make_float4(acc[i][4], acc[i][5], acc[i][6], acc[i][7]);
    }
}

// ---------------------------------------------------------------------------
// Kernel 4: y = FHT(y_rht) * SU * Wscale / 64
// (Wscale commutes through the linear FHT, folded into the epilogue scale)
// ---------------------------------------------------------------------------
__global__ __launch_bounds__(1024) void fht_post_kernel(
    float* __restrict__ out, const float* __restrict__ SU,
    const float* __restrict__ wscale_p)
{
    __shared__ float s[MDIM];
    const int row = blockIdx.x;
    const int tid = threadIdx.x;
    const float* yr = g_yrht + (size_t)row * MDIM;

#pragma unroll
    for (int k = 0; k < 4; k++) {
        int i = tid + k * 1024;
        s[i] = yr[i];
    }

    for (int h = 1; h < MDIM; h <<= 1) {
        __syncthreads();
#pragma unroll
        for (int r = 0; r < 2; r++) {
            int p = tid + r * 1024;
            int i = ((p & ~(h - 1)) << 1) | (p & (h - 1));
            float a = s[i], b = s[i + h];
            s[i]     = a + b;
            s[i + h] = a - b;
        }
    }
    __syncthreads();

    const float ws = __ldg(wscale_p) * 0.015625f;   // Wscale / sqrt(4096)
    float* o = out + (size_t)row * MDIM;
#pragma unroll
    for (int k = 0; k < 4; k++) {
        int i = tid + k * 1024;
        o[i] = s[i] * (SU[i] * ws);
    }
}

// ---------------------------------------------------------------------------
// Launch
// ---------------------------------------------------------------------------
extern "C" void kernel_launch(void* const* d_in, const int* in_sizes, int n_in,
                              void* d_out, int out_size)
{
    const float* x       = (const float*)d_in[0];
    const int*   Qidxs   = (const int*)  d_in[1];
    const int*   Qidxs2  = (const int*)  d_in[2];
    const float* SU      = (const float*)d_in[3];
    const float* SV      = (const float*)d_in[4];
    const float* cb      = (const float*)d_in[5];
    const float* cb2     = (const float*)d_in[6];
    const float* Wscale  = (const float*)d_in[7];
    const float* irs     = (const float*)d_in[8];
    float* out = (float*)d_out;

    (void)in_sizes; (void)n_in; (void)out_size;

    // 1) x_rht = FHT(x*SV)/64
    fht_pre_kernel<<<BATCH, 1024>>>(x, SV);

    // 2) W dequant (independent of 1; same stream is fine)
    dequant_kernel<<<(NGRP + 255) / 256, 256>>>(Qidxs, Qidxs2, cb, cb2, irs);

    // 3) y_rht = x_rht @ W^T
    dim3 grid(MDIM / 128, BATCH / 128);
    sgemm_kernel<<<grid, 256>>>();

    // 4) y = FHT(y_rht) * SU * Wscale / 64
    fht_post_kernel<<<BATCH, 1024>>>(out, SU, Wscale);
}

// round 4
// speedup vs baseline: 3.5500x; 3.5500x over previous
#include <cuda_runtime.h>
#include <cstdint>

// ---------------------------------------------------------------------------
// Problem dims (fixed by the dataset)
// ---------------------------------------------------------------------------
#define BATCH 8192
#define NDIM  4096   // K of the GEMM
#define MDIM  4096
#define NGRP  (MDIM * 512)

// GEMM tiling
#define CTA_M 128
#define CTA_N 128
#define BK    32
#define KCHUNKS (NDIM / BK)        // 128
#define STAGES 3
#define SROW  36                   // padded row stride (floats) -> conflict-free frags
#define STG_FLTS (128 * SROW)      // 4608 floats per matrix per stage
#define DYN_SMEM (2 * STAGES * STG_FLTS * 4)   // 110592 B

// ---------------------------------------------------------------------------
// Scratch (allocation-free __device__ globals)
// ---------------------------------------------------------------------------
__device__ float g_xrht[(size_t)BATCH * NDIM];   // tf32-rounded
__device__ float g_W   [(size_t)MDIM  * NDIM];   // tf32-rounded
__device__ float g_yrht[(size_t)BATCH * MDIM];   // fp32

// ---------------------------------------------------------------------------
// Helpers
// ---------------------------------------------------------------------------
__device__ __forceinline__ uint32_t smem_u32(const void* p) {
    uint32_t a;
    asm("{ .reg .u64 t; cvta.to.shared.u64 t, %1; cvt.u32.u64 %0, t; }" : "=r"(a) : "l"(p));
    return a;
}
__device__ __forceinline__ float to_tf32(float v) {
    float r; asm("cvt.rna.tf32.f32 %0, %1;" : "=f"(r) : "f"(v)); return r;
}
__device__ __forceinline__ void cp_async16(uint32_t dst, const void* src) {
    asm volatile("cp.async.cg.shared.global [%0], [%1], 16;" :: "r"(dst), "l"(src));
}
__device__ __forceinline__ void cp_commit() {
    asm volatile("cp.async.commit_group;" ::: "memory");
}
template <int N>
__device__ __forceinline__ void cp_wait() {
    asm volatile("cp.async.wait_group %0;" :: "n"(N) : "memory");
}
__device__ __forceinline__ void mma_tf32(float* d, const uint32_t* a, const uint32_t* b) {
    asm volatile(
        "mma.sync.aligned.m16n8k8.row.col.f32.tf32.tf32.f32 "
        "{%0,%1,%2,%3}, {%4,%5,%6,%7}, {%8,%9}, {%0,%1,%2,%3};"
        : "+f"(d[0]), "+f"(d[1]), "+f"(d[2]), "+f"(d[3])
        : "r"(a[0]), "r"(a[1]), "r"(a[2]), "r"(a[3]), "r"(b[0]), "r"(b[1]));
}

// ---------------------------------------------------------------------------
// Kernel 1: x_rht = tf32(FHT(x * SV) / 64)
// ---------------------------------------------------------------------------
__global__ __launch_bounds__(1024) void fht_pre_kernel(
    const float* __restrict__ x, const float* __restrict__ SV)
{
    __shared__ float s[NDIM];
    const int row = blockIdx.x;
    const int tid = threadIdx.x;
    const float* xr = x + (size_t)row * NDIM;

#pragma unroll
    for (int k = 0; k < 4; k++) {
        int i = tid + k * 1024;
        s[i] = xr[i] * SV[i];
    }
    for (int h = 1; h < NDIM; h <<= 1) {
        __syncthreads();
#pragma unroll
        for (int r = 0; r < 2; r++) {
            int p = tid + r * 1024;
            int i = ((p & ~(h - 1)) << 1) | (p & (h - 1));
            float a = s[i], b = s[i + h];
            s[i] = a + b;
            s[i + h] = a - b;
        }
    }
    __syncthreads();
    float* o = g_xrht + (size_t)row * NDIM;
#pragma unroll
    for (int k = 0; k < 4; k++) {
        int i = tid + k * 1024;
        o[i] = to_tf32(s[i] * 0.015625f);
    }
}

// ---------------------------------------------------------------------------
// Kernel 2: dequantize W (tf32-rounded)
// ---------------------------------------------------------------------------
__global__ __launch_bounds__(256) void dequant_kernel(
    const int* __restrict__ Qidxs, const int* __restrict__ Qidxs2,
    const float* __restrict__ cb, const float* __restrict__ cb2,
    const float* __restrict__ irs_p)
{
    int g = blockIdx.x * blockDim.x + threadIdx.x;
    if (g >= NGRP) return;
    const float irs = __ldg(irs_p);
    const int q  = Qidxs[g];
    const int q2 = Qidxs2[g];

    float4 c0 = __ldg((const float4*)cb  + q  * 2);
    float4 c1 = __ldg((const float4*)cb  + q  * 2 + 1);
    float4 d0 = __ldg((const float4*)cb2 + q2 * 2);
    float4 d1 = __ldg((const float4*)cb2 + q2 * 2 + 1);

    float4 w0, w1;
    w0.x = to_tf32(fmaf(irs, d0.x, c0.x));  w0.y = to_tf32(fmaf(irs, d0.y, c0.y));
    w0.z = to_tf32(fmaf(irs, d0.z, c0.z));  w0.w = to_tf32(fmaf(irs, d0.w, c0.w));
    w1.x = to_tf32(fmaf(irs, d1.x, c1.x));  w1.y = to_tf32(fmaf(irs, d1.y, c1.y));
    w1.z = to_tf32(fmaf(irs, d1.z, c1.z));  w1.w = to_tf32(fmaf(irs, d1.w, c1.w));

    ((float4*)g_W)[(size_t)g * 2]     = w0;
    ((float4*)g_W)[(size_t)g * 2 + 1] = w1;
}

// ---------------------------------------------------------------------------
// Kernel 3: tf32 mma.sync GEMM  y_rht[B, M] = x_rht @ W^T
// CTA 128x128, 4 warps (2x2), warp tile 64x64, BK=32, 3-stage cp.async.
// ---------------------------------------------------------------------------
__global__ __launch_bounds__(128, 2) void gemm_tf32_kernel()
{
    extern __shared__ float sm[];   // [A stages | B stages]

    const int tid  = threadIdx.x;
    const int wid  = tid >> 5;
    const int lane = tid & 31;
    const int gid  = lane >> 2;     // 0..7
    const int tig  = lane & 3;      // 0..3
    const int wm   = (wid >> 1) * 64;
    const int wn   = (wid & 1) * 64;

    const int brow = blockIdx.y * CTA_M;
    const int bcol = blockIdx.x * CTA_N;

    const uint32_t sbase = smem_u32(sm);

    float acc[4][8][4];
#pragma unroll
    for (int i = 0; i < 4; i++)
#pragma unroll
        for (int j = 0; j < 8; j++)
#pragma unroll
            for (int q = 0; q < 4; q++) acc[i][j][q] = 0.0f;

    // stage loader: 8 cp.asyncs for A + 8 for B per thread, fully coalesced
    auto load_stage = [&](int st, int kc) {
        const int k0 = kc * BK;
        const uint32_t bA = sbase + (uint32_t)st * STG_FLTS * 4;
        const uint32_t bB = sbase + (uint32_t)(STAGES + st) * STG_FLTS * 4;
#pragma unroll
        for (int s = 0; s < 8; s++) {
            int c = s * 128 + tid;
            int row = c >> 3, seg = c & 7;
            cp_async16(bA + (row * SROW + seg * 4) * 4,
                       g_xrht + (size_t)(brow + row) * NDIM + k0 + seg * 4);
            cp_async16(bB + (row * SROW + seg * 4) * 4,
                       g_W    + (size_t)(bcol + row) * NDIM + k0 + seg * 4);
        }
    };

    // prologue: stages 0..STAGES-2
#pragma unroll
    for (int s = 0; s < STAGES - 1; s++) {
        load_stage(s, s);
        cp_commit();
    }

    for (int kc = 0; kc < KCHUNKS; kc++) {
        cp_wait<STAGES - 2>();
        __syncthreads();

        if (kc + STAGES - 1 < KCHUNKS)
            load_stage((kc + STAGES - 1) % STAGES, kc + STAGES - 1);
        cp_commit();

        const int st = kc % STAGES;
        const float* Ast = sm + (size_t)st * STG_FLTS;
        const float* Bst = sm + (size_t)(STAGES + st) * STG_FLTS;

#pragma unroll
        for (int ks = 0; ks < 4; ks++) {
            const int k = ks * 8;
            uint32_t af[4][4], bf[8][2];
#pragma unroll
            for (int i = 0; i < 4; i++) {
                const float* ap = Ast + (wm + i * 16 + gid) * SROW + k + tig;
                af[i][0] = __float_as_uint(ap[0]);
                af[i][1] = __float_as_uint(ap[8 * SROW]);
                af[i][2] = __float_as_uint(ap[4]);
                af[i][3] = __float_as_uint(ap[8 * SROW + 4]);
            }
#pragma unroll
            for (int j = 0; j < 8; j++) {
                const float* bp = Bst + (wn + j * 8 + gid) * SROW + k + tig;
                bf[j][0] = __float_as_uint(bp[0]);
                bf[j][1] = __float_as_uint(bp[4]);
            }
#pragma unroll
            for (int i = 0; i < 4; i++)
#pragma unroll
                for (int j = 0; j < 8; j++)
                    mma_tf32(acc[i][j], af[i], bf[j]);
        }
    }

    // epilogue: fp32 y_rht
#pragma unroll
    for (int i = 0; i < 4; i++) {
        const int r0 = brow + wm + i * 16 + gid;
#pragma unroll
        for (int j = 0; j < 8; j++) {
            const int c0 = bcol + wn + j * 8 + tig * 2;
            *(float2*)&g_yrht[(size_t)r0 * MDIM + c0] =
                make_float2(acc[i][j][0], acc[i][j][1]);
            *(float2*)&g_yrht[(size_t)(r0 + 8) * MDIM + c0] =
                make_float2(acc[i][j][2], acc[i][j][3]);
        }
    }
}

// ---------------------------------------------------------------------------
// Kernel 4: y = FHT(y_rht) * SU * Wscale / 64
// ---------------------------------------------------------------------------
__global__ __launch_bounds__(1024) void fht_post_kernel(
    float* __restrict__ out, const float* __restrict__ SU,
    const float* __restrict__ wscale_p)
{
    __shared__ float s[MDIM];
    const int row = blockIdx.x;
    const int tid = threadIdx.x;
    const float* yr = g_yrht + (size_t)row * MDIM;

#pragma unroll
    for (int k = 0; k < 4; k++) {
        int i = tid + k * 1024;
        s[i] = yr[i];
    }
    for (int h = 1; h < MDIM; h <<= 1) {
        __syncthreads();
#pragma unroll
        for (int r = 0; r < 2; r++) {
            int p = tid + r * 1024;
            int i = ((p & ~(h - 1)) << 1) | (p & (h - 1));
            float a = s[i], b = s[i + h];
            s[i] = a + b;
            s[i + h] = a - b;
        }
    }
    __syncthreads();
    const float ws = __ldg(wscale_p) * 0.015625f;
    float* o = out + (size_t)row * MDIM;
#pragma unroll
    for (int k = 0; k < 4; k++) {
        int i = tid + k * 1024;
        o[i] = s[i] * (SU[i] * ws);
    }
}

// ---------------------------------------------------------------------------
// Launch
// ---------------------------------------------------------------------------
extern "C" void kernel_launch(void* const* d_in, const int* in_sizes, int n_in,
                              void* d_out, int out_size)
{
    const float* x      = (const float*)d_in[0];
    const int*   Qidxs  = (const int*)  d_in[1];
    const int*   Qidxs2 = (const int*)  d_in[2];
    const float* SU     = (const float*)d_in[3];
    const float* SV     = (const float*)d_in[4];
    const float* cb     = (const float*)d_in[5];
    const float* cb2    = (const float*)d_in[6];
    const float* Wscale = (const float*)d_in[7];
    const float* irs    = (const float*)d_in[8];
    float* out = (float*)d_out;
    (void)in_sizes; (void)n_in; (void)out_size;

    cudaFuncSetAttribute(gemm_tf32_kernel,
                         cudaFuncAttributeMaxDynamicSharedMemorySize, DYN_SMEM);

    fht_pre_kernel<<<BATCH, 1024>>>(x, SV);
    dequant_kernel<<<(NGRP + 255) / 256, 256>>>(Qidxs, Qidxs2, cb, cb2, irs);

    dim3 grid(MDIM / CTA_N, BATCH / CTA_M);
    gemm_tf32_kernel<<<grid, 128, DYN_SMEM>>>();

    fht_post_kernel<<<BATCH, 1024>>>(out, SU, Wscale);
}

// round 5
// speedup vs baseline: 6.6581x; 1.8755x over previous
#include <cuda_runtime.h>
#include <cuda_fp16.h>
#include <cstdint>

// ---------------------------------------------------------------------------
// Problem dims (fixed by the dataset)
// ---------------------------------------------------------------------------
#define BATCH 8192
#define NDIM  4096   // K of the GEMM
#define MDIM  4096
#define NGRP  (MDIM * 512)

// GEMM tiling (fp16 operands, fp32 accum)
#define CTA_M 128
#define CTA_N 128
#define BKH   64                    // K halves per chunk = 128 B per row
#define KCHUNKS (NDIM / BKH)        // 64
#define STAGES 3
#define SROWH 72                    // padded row stride in halves (144 B)
#define STG_BYTES (128 * SROWH * 2) // 18432 B per matrix per stage
#define DYN_SMEM (2 * STAGES * STG_BYTES)   // 110592 B

// ---------------------------------------------------------------------------
// Scratch (allocation-free __device__ globals)
// ---------------------------------------------------------------------------
__device__ __half g_xrht[(size_t)BATCH * NDIM];  // 64 MB
__device__ __half g_W   [(size_t)MDIM  * NDIM];  // 32 MB
__device__ float  g_yrht[(size_t)BATCH * MDIM];  // 128 MB

// ---------------------------------------------------------------------------
// Helpers
// ---------------------------------------------------------------------------
__device__ __forceinline__ uint32_t smem_u32(const void* p) {
    uint32_t a;
    asm("{ .reg .u64 t; cvta.to.shared.u64 t, %1; cvt.u32.u64 %0, t; }" : "=r"(a) : "l"(p));
    return a;
}
__device__ __forceinline__ void cp_async16(uint32_t dst, const void* src) {
    asm volatile("cp.async.cg.shared.global [%0], [%1], 16;" :: "r"(dst), "l"(src));
}
__device__ __forceinline__ void cp_commit() {
    asm volatile("cp.async.commit_group;" ::: "memory");
}
template <int N>
__device__ __forceinline__ void cp_wait() {
    asm volatile("cp.async.wait_group %0;" :: "n"(N) : "memory");
}
__device__ __forceinline__ void mma_f16(float* d, const uint32_t* a, const uint32_t* b) {
    asm volatile(
        "mma.sync.aligned.m16n8k16.row.col.f32.f16.f16.f32 "
        "{%0,%1,%2,%3}, {%4,%5,%6,%7}, {%8,%9}, {%0,%1,%2,%3};"
        : "+f"(d[0]), "+f"(d[1]), "+f"(d[2]), "+f"(d[3])
        : "r"(a[0]), "r"(a[1]), "r"(a[2]), "r"(a[3]), "r"(b[0]), "r"(b[1]));
}
// radix-4 Hadamard butterfly (two radix-2 stages fused)
__device__ __forceinline__ void bfly4(float& e0, float& e1, float& e2, float& e3) {
    float u0 = e0 + e1, u1 = e0 - e1, u2 = e2 + e3, u3 = e2 - e3;
    e0 = u0 + u2; e1 = u1 + u3; e2 = u0 - u2; e3 = u1 - u3;
}

// ---------------------------------------------------------------------------
// Kernel 1: x_rht = fp16(FHT(x * SV) / 64)  — radix-4, 1 reg stage + 5 smem passes
// ---------------------------------------------------------------------------
__global__ __launch_bounds__(1024) void fht_pre_kernel(
    const float* __restrict__ x, const float* __restrict__ SV)
{
    __shared__ float s[NDIM];
    const int row = blockIdx.x;
    const int t = threadIdx.x;

    float4 v = *(const float4*)(x + (size_t)row * NDIM + 4 * t);
    float4 sv = *(const float4*)(SV + 4 * t);
    float e0 = v.x * sv.x, e1 = v.y * sv.y, e2 = v.z * sv.z, e3 = v.w * sv.w;
    bfly4(e0, e1, e2, e3);                       // stages h=1,2
    *(float4*)(s + 4 * t) = make_float4(e0, e1, e2, e3);

#pragma unroll
    for (int h = 4; h < NDIM; h <<= 2) {          // h = 4,16,64,256,1024
        __syncthreads();
        int base = (t / h) * (4 * h) + (t % h);
        float a0 = s[base], a1 = s[base + h], a2 = s[base + 2 * h], a3 = s[base + 3 * h];
        bfly4(a0, a1, a2, a3);
        s[base] = a0; s[base + h] = a1; s[base + 2 * h] = a2; s[base + 3 * h] = a3;
    }
    __syncthreads();

    float4 r = *(const float4*)(s + 4 * t);
    const float sc = 0.015625f;                   // 1/sqrt(4096)
    __half2 p0 = __floats2half2_rn(r.x * sc, r.y * sc);
    __half2 p1 = __floats2half2_rn(r.z * sc, r.w * sc);
    uint2 u;
    u.x = *reinterpret_cast<uint32_t*>(&p0);
    u.y = *reinterpret_cast<uint32_t*>(&p1);
    *(uint2*)(g_xrht + (size_t)row * NDIM + 4 * t) = u;
}

// ---------------------------------------------------------------------------
// Kernel 2: dequantize W -> fp16
// ---------------------------------------------------------------------------
__global__ __launch_bounds__(256) void dequant_kernel(
    const int* __restrict__ Qidxs, const int* __restrict__ Qidxs2,
    const float* __restrict__ cb, const float* __restrict__ cb2,
    const float* __restrict__ irs_p)
{
    int g = blockIdx.x * blockDim.x + threadIdx.x;
    if (g >= NGRP) return;
    const float irs = __ldg(irs_p);
    const int q  = Qidxs[g];
    const int q2 = Qidxs2[g];

    float4 c0 = __ldg((const float4*)cb  + q  * 2);
    float4 c1 = __ldg((const float4*)cb  + q  * 2 + 1);
    float4 d0 = __ldg((const float4*)cb2 + q2 * 2);
    float4 d1 = __ldg((const float4*)cb2 + q2 * 2 + 1);

    __half2 h0 = __floats2half2_rn(fmaf(irs, d0.x, c0.x), fmaf(irs, d0.y, c0.y));
    __half2 h1 = __floats2half2_rn(fmaf(irs, d0.z, c0.z), fmaf(irs, d0.w, c0.w));
    __half2 h2 = __floats2half2_rn(fmaf(irs, d1.x, c1.x), fmaf(irs, d1.y, c1.y));
    __half2 h3 = __floats2half2_rn(fmaf(irs, d1.z, c1.z), fmaf(irs, d1.w, c1.w));

    uint4 u;
    u.x = *reinterpret_cast<uint32_t*>(&h0);
    u.y = *reinterpret_cast<uint32_t*>(&h1);
    u.z = *reinterpret_cast<uint32_t*>(&h2);
    u.w = *reinterpret_cast<uint32_t*>(&h3);
    *(uint4*)(g_W + (size_t)g * 8) = u;
}

// ---------------------------------------------------------------------------
// Kernel 3: fp16 mma.sync GEMM  y_rht[B, M] = x_rht @ W^T  (fp32 accum)
// CTA 128x128, 4 warps (2x2), warp tile 64x64, BKH=64, 3-stage cp.async.
// ---------------------------------------------------------------------------
__global__ __launch_bounds__(128, 2) void gemm_f16_kernel()
{
    extern __shared__ __half smh[];   // [A stages | B stages]

    const int tid  = threadIdx.x;
    const int wid  = tid >> 5;
    const int lane = tid & 31;
    const int gid  = lane >> 2;     // 0..7
    const int tig  = lane & 3;      // 0..3
    const int wm   = (wid >> 1) * 64;
    const int wn   = (wid & 1) * 64;

    const int brow = blockIdx.y * CTA_M;
    const int bcol = blockIdx.x * CTA_N;

    const uint32_t sbase = smem_u32(smh);

    float acc[4][8][4];
#pragma unroll
    for (int i = 0; i < 4; i++)
#pragma unroll
        for (int j = 0; j < 8; j++)
#pragma unroll
            for (int q = 0; q < 4; q++) acc[i][j][q] = 0.0f;

    // stage loader: 8 cp.asyncs for A + 8 for B per thread (16B each), coalesced
    auto load_stage = [&](int st, int kc) {
        const int k0 = kc * BKH;
        const uint32_t bA = sbase + (uint32_t)st * STG_BYTES;
        const uint32_t bB = sbase + (uint32_t)(STAGES + st) * STG_BYTES;
#pragma unroll
        for (int s = 0; s < 8; s++) {
            int c = s * 128 + tid;
            int row = c >> 3, seg = c & 7;
            cp_async16(bA + row * (SROWH * 2) + seg * 16,
                       g_xrht + (size_t)(brow + row) * NDIM + k0 + seg * 8);
            cp_async16(bB + row * (SROWH * 2) + seg * 16,
                       g_W    + (size_t)(bcol + row) * NDIM + k0 + seg * 8);
        }
    };

#pragma unroll
    for (int s = 0; s < STAGES - 1; s++) {
        load_stage(s, s);
        cp_commit();
    }

    for (int kc = 0; kc < KCHUNKS; kc++) {
        cp_wait<STAGES - 2>();
        __syncthreads();

        if (kc + STAGES - 1 < KCHUNKS)
            load_stage((kc + STAGES - 1) % STAGES, kc + STAGES - 1);
        cp_commit();

        const int st = kc % STAGES;
        const __half* Ast = smh + (size_t)st * 128 * SROWH;
        const __half* Bst = smh + (size_t)(STAGES + st) * 128 * SROWH;

#pragma unroll
        for (int ks = 0; ks < 4; ks++) {
            const int k = ks * 16;
            uint32_t af[4][4], bf[8][2];
#pragma unroll
            for (int i = 0; i < 4; i++) {
                const __half* ap = Ast + (wm + i * 16 + gid) * SROWH + k + tig * 2;
                af[i][0] = *(const uint32_t*)(ap);
                af[i][1] = *(const uint32_t*)(ap + 8 * SROWH);
                af[i][2] = *(const uint32_t*)(ap + 8);
                af[i][3] = *(const uint32_t*)(ap + 8 * SROWH + 8);
            }
#pragma unroll
            for (int j = 0; j < 8; j++) {
                const __half* bp = Bst + (wn + j * 8 + gid) * SROWH + k + tig * 2;
                bf[j][0] = *(const uint32_t*)(bp);
                bf[j][1] = *(const uint32_t*)(bp + 8);
            }
#pragma unroll
            for (int i = 0; i < 4; i++)
#pragma unroll
                for (int j = 0; j < 8; j++)
                    mma_f16(acc[i][j], af[i], bf[j]);
        }
    }

    // epilogue: fp32 y_rht
#pragma unroll
    for (int i = 0; i < 4; i++) {
        const int r0 = brow + wm + i * 16 + gid;
#pragma unroll
        for (int j = 0; j < 8; j++) {
            const int c0 = bcol + wn + j * 8 + tig * 2;
            *(float2*)&g_yrht[(size_t)r0 * MDIM + c0] =
                make_float2(acc[i][j][0], acc[i][j][1]);
            *(float2*)&g_yrht[(size_t)(r0 + 8) * MDIM + c0] =
                make_float2(acc[i][j][2], acc[i][j][3]);
        }
    }
}

// ---------------------------------------------------------------------------
// Kernel 4: y = FHT(y_rht) * SU * Wscale / 64  — radix-4
// ---------------------------------------------------------------------------
__global__ __launch_bounds__(1024) void fht_post_kernel(
    float* __restrict__ out, const float* __restrict__ SU,
    const float* __restrict__ wscale_p)
{
    __shared__ float s[MDIM];
    const int row = blockIdx.x;
    const int t = threadIdx.x;

    float4 v = *(const float4*)(g_yrht + (size_t)row * MDIM + 4 * t);
    float e0 = v.x, e1 = v.y, e2 = v.z, e3 = v.w;
    bfly4(e0, e1, e2, e3);
    *(float4*)(s + 4 * t) = make_float4(e0, e1, e2, e3);

#pragma unroll
    for (int h = 4; h < MDIM; h <<= 2) {
        __syncthreads();
        int base = (t / h) * (4 * h) + (t % h);
        float a0 = s[base], a1 = s[base + h], a2 = s[base + 2 * h], a3 = s[base + 3 * h];
        bfly4(a0, a1, a2, a3);
        s[base] = a0; s[base + h] = a1; s[base + 2 * h] = a2; s[base + 3 * h] = a3;
    }
    __syncthreads();

    const float ws = __ldg(wscale_p) * 0.015625f;
    float4 r = *(const float4*)(s + 4 * t);
    float4 su = *(const float4*)(SU + 4 * t);
    *(float4*)(out + (size_t)row * MDIM + 4 * t) = make_float4(
        r.x * su.x * ws, r.y * su.y * ws, r.z * su.z * ws, r.w * su.w * ws);
}

// ---------------------------------------------------------------------------
// Launch
// ---------------------------------------------------------------------------
extern "C" void kernel_launch(void* const* d_in, const int* in_sizes, int n_in,
                              void* d_out, int out_size)
{
    const float* x      = (const float*)d_in[0];
    const int*   Qidxs  = (const int*)  d_in[1];
    const int*   Qidxs2 = (const int*)  d_in[2];
    const float* SU     = (const float*)d_in[3];
    const float* SV     = (const float*)d_in[4];
    const float* cb     = (const float*)d_in[5];
    const float* cb2    = (const float*)d_in[6];
    const float* Wscale = (const float*)d_in[7];
    const float* irs    = (const float*)d_in[8];
    float* out = (float*)d_out;
    (void)in_sizes; (void)n_in; (void)out_size;

    cudaFuncSetAttribute(gemm_f16_kernel,
                         cudaFuncAttributeMaxDynamicSharedMemorySize, DYN_SMEM);

    fht_pre_kernel<<<BATCH, 1024>>>(x, SV);
    dequant_kernel<<<(NGRP + 255) / 256, 256>>>(Qidxs, Qidxs2, cb, cb2, irs);

    dim3 grid(MDIM / CTA_N, BATCH / CTA_M);
    gemm_f16_kernel<<<grid, 128, DYN_SMEM>>>();

    fht_post_kernel<<<BATCH, 1024>>>(out, SU, Wscale);
}

// round 6
// speedup vs baseline: 6.7636x; 1.0158x over previous
#include <cuda_runtime.h>
#include <cuda_fp16.h>
#include <cstdint>

// ---------------------------------------------------------------------------
// Problem dims (fixed by the dataset)
// ---------------------------------------------------------------------------
#define BATCH 8192
#define NDIM  4096
#define MDIM  4096
#define NGRP  (MDIM * 512)

// GEMM tiling (fp16 operands, fp32 accum)
#define CTA_M 128
#define CTA_N 128
#define BKH   64
#define KCHUNKS (NDIM / BKH)        // 64
#define STAGES 3
#define SROWH 72                    // padded row stride in halves
#define STG_BYTES (128 * SROWH * 2) // 18432 B
#define DYN_SMEM (2 * STAGES * STG_BYTES)   // 110592 B

// ---------------------------------------------------------------------------
// Scratch
// ---------------------------------------------------------------------------
__device__ __half g_xrht[(size_t)BATCH * NDIM];
__device__ __half g_W   [(size_t)MDIM  * NDIM];
__device__ float  g_yrht[(size_t)BATCH * MDIM];

// ---------------------------------------------------------------------------
// Helpers
// ---------------------------------------------------------------------------
__device__ __forceinline__ uint32_t smem_u32(const void* p) {
    uint32_t a;
    asm("{ .reg .u64 t; cvta.to.shared.u64 t, %1; cvt.u32.u64 %0, t; }" : "=r"(a) : "l"(p));
    return a;
}
__device__ __forceinline__ void cp_async16(uint32_t dst, const void* src) {
    asm volatile("cp.async.cg.shared.global [%0], [%1], 16;" :: "r"(dst), "l"(src));
}
__device__ __forceinline__ void cp_commit() {
    asm volatile("cp.async.commit_group;" ::: "memory");
}
template <int N>
__device__ __forceinline__ void cp_wait() {
    asm volatile("cp.async.wait_group %0;" :: "n"(N) : "memory");
}
__device__ __forceinline__ void mma_f16(float* d, const uint32_t* a, const uint32_t* b) {
    asm volatile(
        "mma.sync.aligned.m16n8k16.row.col.f32.f16.f16.f32 "
        "{%0,%1,%2,%3}, {%4,%5,%6,%7}, {%8,%9}, {%0,%1,%2,%3};"
        : "+f"(d[0]), "+f"(d[1]), "+f"(d[2]), "+f"(d[3])
        : "r"(a[0]), "r"(a[1]), "r"(a[2]), "r"(a[3]), "r"(b[0]), "r"(b[1]));
}
__device__ __forceinline__ void ldsm_x4(uint32_t* r, uint32_t addr) {
    asm volatile("ldmatrix.sync.aligned.m8n8.x4.shared.b16 {%0,%1,%2,%3}, [%4];"
                 : "=r"(r[0]), "=r"(r[1]), "=r"(r[2]), "=r"(r[3]) : "r"(addr));
}
__device__ __forceinline__ void bfly4(float& e0, float& e1, float& e2, float& e3) {
    float u0 = e0 + e1, u1 = e0 - e1, u2 = e2 + e3, u3 = e2 - e3;
    e0 = u0 + u2; e1 = u1 + u3; e2 = u0 - u2; e3 = u1 - u3;
}
// In-register H_16 (4 butterfly stages) on e[0..15]
__device__ __forceinline__ void h16(float* e) {
    bfly4(e[0], e[1], e[2], e[3]);   bfly4(e[4], e[5], e[6], e[7]);
    bfly4(e[8], e[9], e[10], e[11]); bfly4(e[12], e[13], e[14], e[15]);
    bfly4(e[0], e[4], e[8], e[12]);  bfly4(e[1], e[5], e[9], e[13]);
    bfly4(e[2], e[6], e[10], e[14]); bfly4(e[3], e[7], e[11], e[15]);
}

// FHT smem: layout A = i + (i>>4); layout B = i + (i>>8)*16. Max idx 4350.
#define FHT_SMEM 4352

// ---------------------------------------------------------------------------
// Kernel 1: x_rht = fp16(FHT(x*SV)/64) — 3 passes, 16 elems/thread in regs
// ---------------------------------------------------------------------------
__global__ __launch_bounds__(256) void fht_pre_kernel(
    const float* __restrict__ x, const float* __restrict__ SV)
{
    __shared__ float s[FHT_SMEM];
    const int row = blockIdx.x;
    const int t = threadIdx.x;
    float e[16];

    // Pass 1: stages h=1..8 on contiguous 16
    {
        const float* xr = x + (size_t)row * NDIM + t * 16;
        const float* sv = SV + t * 16;
#pragma unroll
        for (int q = 0; q < 4; q++) {
            float4 v = *(const float4*)(xr + 4 * q);
            float4 w = *(const float4*)(sv + 4 * q);
            e[4 * q + 0] = v.x * w.x; e[4 * q + 1] = v.y * w.y;
            e[4 * q + 2] = v.z * w.z; e[4 * q + 3] = v.w * w.w;
        }
        h16(e);
#pragma unroll
        for (int o = 0; o < 16; o++) s[17 * t + o] = e[o];   // layout A
    }
    __syncthreads();

    // Pass 2: stages h=16..128; i = b*256 + j*16 + r
    {
        const int r = t & 15, b = t >> 4;
        const int baseA = b * 272 + r;
#pragma unroll
        for (int j = 0; j < 16; j++) e[j] = s[baseA + j * 17];
        h16(e);
        __syncthreads();
        const int baseB = b * 272 + r;                       // layout B
#pragma unroll
        for (int j = 0; j < 16; j++) s[baseB + j * 16] = e[j];
    }
    __syncthreads();

    // Pass 3: stages h=256..2048; i = j*256 + t
    {
#pragma unroll
        for (int j = 0; j < 16; j++) e[j] = s[j * 272 + t];
        h16(e);
        const float sc = 0.015625f;
        __half* o = g_xrht + (size_t)row * NDIM;
#pragma unroll
        for (int j = 0; j < 16; j++) o[j * 256 + t] = __float2half_rn(e[j] * sc);
    }
}

// ---------------------------------------------------------------------------
// Kernel 2: dequantize W -> fp16
// ---------------------------------------------------------------------------
__global__ __launch_bounds__(256) void dequant_kernel(
    const int* __restrict__ Qidxs, const int* __restrict__ Qidxs2,
    const float* __restrict__ cb, const float* __restrict__ cb2,
    const float* __restrict__ irs_p)
{
    int g = blockIdx.x * blockDim.x + threadIdx.x;
    if (g >= NGRP) return;
    const float irs = __ldg(irs_p);
    const int q  = Qidxs[g];
    const int q2 = Qidxs2[g];

    float4 c0 = __ldg((const float4*)cb  + q  * 2);
    float4 c1 = __ldg((const float4*)cb  + q  * 2 + 1);
    float4 d0 = __ldg((const float4*)cb2 + q2 * 2);
    float4 d1 = __ldg((const float4*)cb2 + q2 * 2 + 1);

    __half2 h0 = __floats2half2_rn(fmaf(irs, d0.x, c0.x), fmaf(irs, d0.y, c0.y));
    __half2 h1 = __floats2half2_rn(fmaf(irs, d0.z, c0.z), fmaf(irs, d0.w, c0.w));
    __half2 h2 = __floats2half2_rn(fmaf(irs, d1.x, c1.x), fmaf(irs, d1.y, c1.y));
    __half2 h3 = __floats2half2_rn(fmaf(irs, d1.z, c1.z), fmaf(irs, d1.w, c1.w));

    uint4 u;
    u.x = *reinterpret_cast<uint32_t*>(&h0);
    u.y = *reinterpret_cast<uint32_t*>(&h1);
    u.z = *reinterpret_cast<uint32_t*>(&h2);
    u.w = *reinterpret_cast<uint32_t*>(&h3);
    *(uint4*)(g_W + (size_t)g * 8) = u;
}

// ---------------------------------------------------------------------------
// Kernel 3: fp16 mma.sync GEMM with ldmatrix fragment loads
// ---------------------------------------------------------------------------
__global__ __launch_bounds__(128, 2) void gemm_f16_kernel()
{
    extern __shared__ __half smh[];

    const int tid  = threadIdx.x;
    const int wid  = tid >> 5;
    const int lane = tid & 31;
    const int gid  = lane >> 2;
    const int tig  = lane & 3;
    const int wm   = (wid >> 1) * 64;
    const int wn   = (wid & 1) * 64;

    const int brow = blockIdx.y * CTA_M;
    const int bcol = blockIdx.x * CTA_N;

    const uint32_t sbase = smem_u32(smh);

    // per-lane ldmatrix base offsets (bytes) within a stage
    const uint32_t lmA = ((uint32_t)(wm + (lane & 15)) * SROWH + (lane >> 4) * 8) * 2;
    const uint32_t lmB = ((uint32_t)(wn + (lane & 15)) * SROWH + (lane >> 4) * 8) * 2;

    float acc[4][8][4];
#pragma unroll
    for (int i = 0; i < 4; i++)
#pragma unroll
        for (int j = 0; j < 8; j++)
#pragma unroll
            for (int q = 0; q < 4; q++) acc[i][j][q] = 0.0f;

    auto load_stage = [&](int st, int kc) {
        const int k0 = kc * BKH;
        const uint32_t bA = sbase + (uint32_t)st * STG_BYTES;
        const uint32_t bB = sbase + (uint32_t)(STAGES + st) * STG_BYTES;
#pragma unroll
        for (int s = 0; s < 8; s++) {
            int c = s * 128 + tid;
            int row = c >> 3, seg = c & 7;
            cp_async16(bA + row * (SROWH * 2) + seg * 16,
                       g_xrht + (size_t)(brow + row) * NDIM + k0 + seg * 8);
            cp_async16(bB + row * (SROWH * 2) + seg * 16,
                       g_W    + (size_t)(bcol + row) * NDIM + k0 + seg * 8);
        }
    };

#pragma unroll
    for (int s = 0; s < STAGES - 1; s++) {
        load_stage(s, s);
        cp_commit();
    }

    for (int kc = 0; kc < KCHUNKS; kc++) {
        cp_wait<STAGES - 2>();
        __syncthreads();

        if (kc + STAGES - 1 < KCHUNKS)
            load_stage((kc + STAGES - 1) % STAGES, kc + STAGES - 1);
        cp_commit();

        const int st = kc % STAGES;
        const uint32_t Ast = sbase + (uint32_t)st * STG_BYTES + lmA;
        const uint32_t Bst = sbase + (uint32_t)(STAGES + st) * STG_BYTES + lmB;

#pragma unroll
        for (int ks = 0; ks < 4; ks++) {
            const uint32_t kb = ks * 32;   // 16 halves = 32 bytes
            uint32_t af[4][4], bf[8][2];
#pragma unroll
            for (int i = 0; i < 4; i++)
                ldsm_x4(af[i], Ast + (uint32_t)i * 16 * SROWH * 2 + kb);
#pragma unroll
            for (int jp = 0; jp < 4; jp++) {
                uint32_t r[4];
                ldsm_x4(r, Bst + (uint32_t)jp * 16 * SROWH * 2 + kb);
                bf[2 * jp][0] = r[0]; bf[2 * jp + 1][0] = r[1];
                bf[2 * jp][1] = r[2]; bf[2 * jp + 1][1] = r[3];
            }
#pragma unroll
            for (int i = 0; i < 4; i++)
#pragma unroll
                for (int j = 0; j < 8; j++)
                    mma_f16(acc[i][j], af[i], bf[j]);
        }
    }

#pragma unroll
    for (int i = 0; i < 4; i++) {
        const int r0 = brow + wm + i * 16 + gid;
#pragma unroll
        for (int j = 0; j < 8; j++) {
            const int c0 = bcol + wn + j * 8 + tig * 2;
            *(float2*)&g_yrht[(size_t)r0 * MDIM + c0] =
                make_float2(acc[i][j][0], acc[i][j][1]);
            *(float2*)&g_yrht[(size_t)(r0 + 8) * MDIM + c0] =
                make_float2(acc[i][j][2], acc[i][j][3]);
        }
    }
}

// ---------------------------------------------------------------------------
// Kernel 4: y = FHT(y_rht) * SU * Wscale / 64 — 3-pass register FHT
// ---------------------------------------------------------------------------
__global__ __launch_bounds__(256) void fht_post_kernel(
    float* __restrict__ out, const float* __restrict__ SU,
    const float* __restrict__ wscale_p)
{
    __shared__ float s[FHT_SMEM];
    const int row = blockIdx.x;
    const int t = threadIdx.x;
    float e[16];

    {
        const float* yr = g_yrht + (size_t)row * MDIM + t * 16;
#pragma unroll
        for (int q = 0; q < 4; q++) {
            float4 v = *(const float4*)(yr + 4 * q);
            e[4 * q + 0] = v.x; e[4 * q + 1] = v.y;
            e[4 * q + 2] = v.z; e[4 * q + 3] = v.w;
        }
        h16(e);
#pragma unroll
        for (int o = 0; o < 16; o++) s[17 * t + o] = e[o];
    }
    __syncthreads();

    {
        const int r = t & 15, b = t >> 4;
        const int baseA = b * 272 + r;
#pragma unroll
        for (int j = 0; j < 16; j++) e[j] = s[baseA + j * 17];
        h16(e);
        __syncthreads();
        const int baseB = b * 272 + r;
#pragma unroll
        for (int j = 0; j < 16; j++) s[baseB + j * 16] = e[j];
    }
    __syncthreads();

    {
#pragma unroll
        for (int j = 0; j < 16; j++) e[j] = s[j * 272 + t];
        h16(e);
        const float ws = __ldg(wscale_p) * 0.015625f;
        float* o = out + (size_t)row * MDIM;
#pragma unroll
        for (int j = 0; j < 16; j++)
            o[j * 256 + t] = e[j] * SU[j * 256 + t] * ws;
    }
}

// ---------------------------------------------------------------------------
// Launch
// ---------------------------------------------------------------------------
extern "C" void kernel_launch(void* const* d_in, const int* in_sizes, int n_in,
                              void* d_out, int out_size)
{
    const float* x      = (const float*)d_in[0];
    const int*   Qidxs  = (const int*)  d_in[1];
    const int*   Qidxs2 = (const int*)  d_in[2];
    const float* SU     = (const float*)d_in[3];
    const float* SV     = (const float*)d_in[4];
    const float* cb     = (const float*)d_in[5];
    const float* cb2    = (const float*)d_in[6];
    const float* Wscale = (const float*)d_in[7];
    const float* irs    = (const float*)d_in[8];
    float* out = (float*)d_out;
    (void)in_sizes; (void)n_in; (void)out_size;

    cudaFuncSetAttribute(gemm_f16_kernel,
                         cudaFuncAttributeMaxDynamicSharedMemorySize, DYN_SMEM);

    fht_pre_kernel<<<BATCH, 256>>>(x, SV);
    dequant_kernel<<<(NGRP + 255) / 256, 256>>>(Qidxs, Qidxs2, cb, cb2, irs);

    dim3 grid(MDIM / CTA_N, BATCH / CTA_M);
    gemm_f16_kernel<<<grid, 128, DYN_SMEM>>>();

    fht_post_kernel<<<BATCH, 256>>>(out, SU, Wscale);
}

// round 9
// speedup vs baseline: 7.3407x; 1.0853x over previous
#include <cuda_runtime.h>
#include <cuda_fp16.h>
#include <cstdint>

// ---------------------------------------------------------------------------
// Problem dims (fixed by the dataset)
// ---------------------------------------------------------------------------
#define BATCH 8192
#define NDIM  4096
#define MDIM  4096
#define NGRP  (MDIM * 512)

// GEMM tiling (fp16 operands, fp32 accum)
#define CTA_M 128
#define CTA_N 128
#define BKH   64
#define KCHUNKS (NDIM / BKH)        // 64
#define STAGES 3
#define SROWH 72                    // padded row stride in halves
#define STG_BYTES (128 * SROWH * 2) // 18432 B
#define DYN_SMEM (2 * STAGES * STG_BYTES)   // 110592 B

// ---------------------------------------------------------------------------
// Scratch (16B-aligned for vector/cp.async access)
// ---------------------------------------------------------------------------
__device__ __align__(16) __half g_xrht[(size_t)BATCH * NDIM];  // 64 MB
__device__ __align__(16) __half g_W   [(size_t)MDIM  * NDIM];  // 32 MB
__device__ __align__(16) float  g_yrht[(size_t)BATCH * MDIM];  // 128 MB

// ---------------------------------------------------------------------------
// Helpers
// ---------------------------------------------------------------------------
__device__ __forceinline__ uint32_t smem_u32(const void* p) {
    uint32_t a;
    asm("{ .reg .u64 t; cvta.to.shared.u64 t, %1; cvt.u32.u64 %0, t; }" : "=r"(a) : "l"(p));
    return a;
}
__device__ __forceinline__ void cp_async16(uint32_t dst, const void* src) {
    asm volatile("cp.async.cg.shared.global [%0], [%1], 16;" :: "r"(dst), "l"(src));
}
__device__ __forceinline__ void cp_commit() {
    asm volatile("cp.async.commit_group;" ::: "memory");
}
template <int N>
__device__ __forceinline__ void cp_wait() {
    asm volatile("cp.async.wait_group %0;" :: "n"(N) : "memory");
}
__device__ __forceinline__ void mma_f16(float* d, const uint32_t* a, const uint32_t* b) {
    asm volatile(
        "mma.sync.aligned.m16n8k16.row.col.f32.f16.f16.f32 "
        "{%0,%1,%2,%3}, {%4,%5,%6,%7}, {%8,%9}, {%0,%1,%2,%3};"
        : "+f"(d[0]), "+f"(d[1]), "+f"(d[2]), "+f"(d[3])
        : "r"(a[0]), "r"(a[1]), "r"(a[2]), "r"(a[3]), "r"(b[0]), "r"(b[1]));
}
__device__ __forceinline__ void bfly4(float& e0, float& e1, float& e2, float& e3) {
    float u0 = e0 + e1, u1 = e0 - e1, u2 = e2 + e3, u3 = e2 - e3;
    e0 = u0 + u2; e1 = u1 + u3; e2 = u0 - u2; e3 = u1 - u3;
}
// In-register H_16 (4 butterfly stages) on e[0..15]
__device__ __forceinline__ void h16(float* e) {
    bfly4(e[0], e[1], e[2], e[3]);   bfly4(e[4], e[5], e[6], e[7]);
    bfly4(e[8], e[9], e[10], e[11]); bfly4(e[12], e[13], e[14], e[15]);
    bfly4(e[0], e[4], e[8], e[12]);  bfly4(e[1], e[5], e[9], e[13]);
    bfly4(e[2], e[6], e[10], e[14]); bfly4(e[3], e[7], e[11], e[15]);
}

// FHT smem: layout A = i + (i>>4); layout B = i + (i>>8)*16. Max idx 4350.
#define FHT_SMEM 4352

// ---------------------------------------------------------------------------
// Kernel 1: x_rht = fp16(FHT(x*SV)/64) — 3 passes, 16 elems/thread in regs
// ---------------------------------------------------------------------------
__global__ __launch_bounds__(256) void fht_pre_kernel(
    const float* __restrict__ x, const float* __restrict__ SV)
{
    __shared__ float s[FHT_SMEM];
    const int row = blockIdx.x;
    const int t = threadIdx.x;
    float e[16];

    // Pass 1: stages h=1..8 on contiguous 16
    {
        const float* xr = x + (size_t)row * NDIM + t * 16;
        const float* sv = SV + t * 16;
#pragma unroll
        for (int q = 0; q < 4; q++) {
            float4 v = *(const float4*)(xr + 4 * q);
            float4 w = *(const float4*)(sv + 4 * q);
            e[4 * q + 0] = v.x * w.x; e[4 * q + 1] = v.y * w.y;
            e[4 * q + 2] = v.z * w.z; e[4 * q + 3] = v.w * w.w;
        }
        h16(e);
#pragma unroll
        for (int o = 0; o < 16; o++) s[17 * t + o] = e[o];   // layout A
    }
    __syncthreads();

    // Pass 2: stages h=16..128; i = b*256 + j*16 + r
    {
        const int r = t & 15, b = t >> 4;
        const int baseA = b * 272 + r;
#pragma unroll
        for (int j = 0; j < 16; j++) e[j] = s[baseA + j * 17];
        h16(e);
        __syncthreads();
        const int baseB = b * 272 + r;                       // layout B
#pragma unroll
        for (int j = 0; j < 16; j++) s[baseB + j * 16] = e[j];
    }
    __syncthreads();

    // Pass 3: stages h=256..2048; i = j*256 + t
    {
#pragma unroll
        for (int j = 0; j < 16; j++) e[j] = s[j * 272 + t];
        h16(e);
        const float sc = 0.015625f;
        __half* o = g_xrht + (size_t)row * NDIM;
#pragma unroll
        for (int j = 0; j < 16; j++) o[j * 256 + t] = __float2half_rn(e[j] * sc);
    }
}

// ---------------------------------------------------------------------------
// Kernel 2: dequantize W -> fp16
// ---------------------------------------------------------------------------
__global__ __launch_bounds__(256) void dequant_kernel(
    const int* __restrict__ Qidxs, const int* __restrict__ Qidxs2,
    const float* __restrict__ cb, const float* __restrict__ cb2,
    const float* __restrict__ irs_p)
{
    int g = blockIdx.x * blockDim.x + threadIdx.x;
    if (g >= NGRP) return;
    const float irs = __ldg(irs_p);
    const int q  = Qidxs[g];
    const int q2 = Qidxs2[g];

    float4 c0 = __ldg((const float4*)cb  + q  * 2);
    float4 c1 = __ldg((const float4*)cb  + q  * 2 + 1);
    float4 d0 = __ldg((const float4*)cb2 + q2 * 2);
    float4 d1 = __ldg((const float4*)cb2 + q2 * 2 + 1);

    __half2 h0 = __floats2half2_rn(fmaf(irs, d0.x, c0.x), fmaf(irs, d0.y, c0.y));
    __half2 h1 = __floats2half2_rn(fmaf(irs, d0.z, c0.z), fmaf(irs, d0.w, c0.w));
    __half2 h2 = __floats2half2_rn(fmaf(irs, d1.x, c1.x), fmaf(irs, d1.y, c1.y));
    __half2 h3 = __floats2half2_rn(fmaf(irs, d1.z, c1.z), fmaf(irs, d1.w, c1.w));

    uint4 u;
    u.x = *reinterpret_cast<uint32_t*>(&h0);
    u.y = *reinterpret_cast<uint32_t*>(&h1);
    u.z = *reinterpret_cast<uint32_t*>(&h2);
    u.w = *reinterpret_cast<uint32_t*>(&h3);
    *(uint4*)(g_W + (size_t)g * 8) = u;
}

// ---------------------------------------------------------------------------
// Kernel 3: fp16 mma.sync GEMM (scalar LDS fragment loads — fastest variant)
// CTA 128x128, 4 warps (2x2), warp tile 64x64, BKH=64, 3-stage cp.async.
// ---------------------------------------------------------------------------
__global__ __launch_bounds__(128, 2) void gemm_f16_kernel()
{
    extern __shared__ __half smh[];

    const int tid  = threadIdx.x;
    const int wid  = tid >> 5;
    const int lane = tid & 31;
    const int gid  = lane >> 2;
    const int tig  = lane & 3;
    const int wm   = (wid >> 1) * 64;
    const int wn   = (wid & 1) * 64;

    const int brow = blockIdx.y * CTA_M;
    const int bcol = blockIdx.x * CTA_N;

    const uint32_t sbase = smem_u32(smh);

    float acc[4][8][4];
#pragma unroll
    for (int i = 0; i < 4; i++)
#pragma unroll
        for (int j = 0; j < 8; j++)
#pragma unroll
            for (int q = 0; q < 4; q++) acc[i][j][q] = 0.0f;

    auto load_stage = [&](int st, int kc) {
        const int k0 = kc * BKH;
        const uint32_t bA = sbase + (uint32_t)st * STG_BYTES;
        const uint32_t bB = sbase + (uint32_t)(STAGES + st) * STG_BYTES;
#pragma unroll
        for (int s = 0; s < 8; s++) {
            int c = s * 128 + tid;
            int row = c >> 3, seg = c & 7;
            cp_async16(bA + row * (SROWH * 2) + seg * 16,
                       g_xrht + (size_t)(brow + row) * NDIM + k0 + seg * 8);
            cp_async16(bB + row * (SROWH * 2) + seg * 16,
                       g_W    + (size_t)(bcol + row) * NDIM + k0 + seg * 8);
        }
    };

#pragma unroll
    for (int s = 0; s < STAGES - 1; s++) {
        load_stage(s, s);
        cp_commit();
    }

    for (int kc = 0; kc < KCHUNKS; kc++) {
        cp_wait<STAGES - 2>();
        __syncthreads();

        if (kc + STAGES - 1 < KCHUNKS)
            load_stage((kc + STAGES - 1) % STAGES, kc + STAGES - 1);
        cp_commit();

        const int st = kc % STAGES;
        const __half* Ast = smh + (size_t)st * 128 * SROWH;
        const __half* Bst = smh + (size_t)(STAGES + st) * 128 * SROWH;

#pragma unroll
        for (int ks = 0; ks < 4; ks++) {
            const int k = ks * 16;
            uint32_t af[4][4], bf[8][2];
#pragma unroll
            for (int i = 0; i < 4; i++) {
                const __half* ap = Ast + (wm + i * 16 + gid) * SROWH + k + tig * 2;
                af[i][0] = *(const uint32_t*)(ap);
                af[i][1] = *(const uint32_t*)(ap + 8 * SROWH);
                af[i][2] = *(const uint32_t*)(ap + 8);
                af[i][3] = *(const uint32_t*)(ap + 8 * SROWH + 8);
            }
#pragma unroll
            for (int j = 0; j < 8; j++) {
                const __half* bp = Bst + (wn + j * 8 + gid) * SROWH + k + tig * 2;
                bf[j][0] = *(const uint32_t*)(bp);
                bf[j][1] = *(const uint32_t*)(bp + 8);
            }
#pragma unroll
            for (int i = 0; i < 4; i++)
#pragma unroll
                for (int j = 0; j < 8; j++)
                    mma_f16(acc[i][j], af[i], bf[j]);
        }
    }

    // epilogue: fp32 y_rht
#pragma unroll
    for (int i = 0; i < 4; i++) {
        const int r0 = brow + wm + i * 16 + gid;
#pragma unroll
        for (int j = 0; j < 8; j++) {
            const int c0 = bcol + wn + j * 8 + tig * 2;
            *(float2*)&g_yrht[(size_t)r0 * MDIM + c0] =
                make_float2(acc[i][j][0], acc[i][j][1]);
            *(float2*)&g_yrht[(size_t)(r0 + 8) * MDIM + c0] =
                make_float2(acc[i][j][2], acc[i][j][3]);
        }
    }
}

// ---------------------------------------------------------------------------
// Kernel 4: y = FHT(y_rht) * SU * Wscale / 64 — 3-pass register FHT
// ---------------------------------------------------------------------------
__global__ __launch_bounds__(256) void fht_post_kernel(
    float* __restrict__ out, const float* __restrict__ SU,
    const float* __restrict__ wscale_p)
{
    __shared__ float s[FHT_SMEM];
    const int row = blockIdx.x;
    const int t = threadIdx.x;
    float e[16];

    {
        const float* yr = g_yrht + (size_t)row * MDIM + t * 16;
#pragma unroll
        for (int q = 0; q < 4; q++) {
            float4 v = *(const float4*)(yr + 4 * q);
            e[4 * q + 0] = v.x; e[4 * q + 1] = v.y;
            e[4 * q + 2] = v.z; e[4 * q + 3] = v.w;
        }
        h16(e);
#pragma unroll
        for (int o = 0; o < 16; o++) s[17 * t + o] = e[o];
    }
    __syncthreads();

    {
        const int r = t & 15, b = t >> 4;
        const int baseA = b * 272 + r;
#pragma unroll
        for (int j = 0; j < 16; j++) e[j] = s[baseA + j * 17];
        h16(e);
        __syncthreads();
        const int baseB = b * 272 + r;
#pragma unroll
        for (int j = 0; j < 16; j++) s[baseB + j * 16] = e[j];
    }
    __syncthreads();

    {
#pragma unroll
        for (int j = 0; j < 16; j++) e[j] = s[j * 272 + t];
        h16(e);
        const float ws = __ldg(wscale_p) * 0.015625f;
        float* o = out + (size_t)row * MDIM;
#pragma unroll
        for (int j = 0; j < 16; j++)
            o[j * 256 + t] = e[j] * SU[j * 256 + t] * ws;
    }
}

// ---------------------------------------------------------------------------
// Launch
// ---------------------------------------------------------------------------
extern "C" void kernel_launch(void* const* d_in, const int* in_sizes, int n_in,
                              void* d_out, int out_size)
{
    const float* x      = (const float*)d_in[0];
    const int*   Qidxs  = (const int*)  d_in[1];
    const int*   Qidxs2 = (const int*)  d_in[2];
    const float* SU     = (const float*)d_in[3];
    const float* SV     = (const float*)d_in[4];
    const float* cb     = (const float*)d_in[5];
    const float* cb2    = (const float*)d_in[6];
    const float* Wscale = (const float*)d_in[7];
    const float* irs    = (const float*)d_in[8];
    float* out = (float*)d_out;
    (void)in_sizes; (void)n_in; (void)out_size;

    cudaFuncSetAttribute(gemm_f16_kernel,
                         cudaFuncAttributeMaxDynamicSharedMemorySize, DYN_SMEM);

    fht_pre_kernel<<<BATCH, 256>>>(x, SV);
    dequant_kernel<<<(NGRP + 255) / 256, 256>>>(Qidxs, Qidxs2, cb, cb2, irs);

    dim3 grid(MDIM / CTA_N, BATCH / CTA_M);
    gemm_f16_kernel<<<grid, 128, DYN_SMEM>>>();

    fht_post_kernel<<<BATCH, 256>>>(out, SU, Wscale);
}

// round 14
// speedup vs baseline: 7.3952x; 1.0074x over previous
#include <cuda_runtime.h>
#include <cuda_fp16.h>
#include <cstdint>

// ---------------------------------------------------------------------------
// Problem dims (fixed by the dataset)
// ---------------------------------------------------------------------------
#define BATCH 8192
#define NDIM  4096
#define MDIM  4096
#define NGRP  (MDIM * 512)

// GEMM tiling (fp16 operands, fp32 accum)
#define CTA_M 128
#define CTA_N 128
#define BKH   64
#define KCHUNKS (NDIM / BKH)        // 64
#define STAGES 3
#define SROWH 72                    // padded row stride in halves
#define STG_BYTES (128 * SROWH * 2) // 18432 B
#define DYN_SMEM (2 * STAGES * STG_BYTES)   // 110592 B

// ---------------------------------------------------------------------------
// Scratch (16B-aligned: vector/cp.async access everywhere)
// ---------------------------------------------------------------------------
__device__ __align__(16) __half g_xrht[(size_t)BATCH * NDIM];  // 64 MB
__device__ __align__(16) __half g_W   [(size_t)MDIM  * NDIM];  // 32 MB
__device__ __align__(16) __half g_yrht[(size_t)BATCH * MDIM];  // 64 MB (fp16)

// ---------------------------------------------------------------------------
// Helpers
// ---------------------------------------------------------------------------
__device__ __forceinline__ uint32_t smem_u32(const void* p) {
    uint32_t a;
    asm("{ .reg .u64 t; cvta.to.shared.u64 t, %1; cvt.u32.u64 %0, t; }" : "=r"(a) : "l"(p));
    return a;
}
__device__ __forceinline__ void cp_async16(uint32_t dst, const void* src) {
    asm volatile("cp.async.cg.shared.global [%0], [%1], 16;" :: "r"(dst), "l"(src));
}
__device__ __forceinline__ void cp_commit() {
    asm volatile("cp.async.commit_group;" ::: "memory");
}
template <int N>
__device__ __forceinline__ void cp_wait() {
    asm volatile("cp.async.wait_group %0;" :: "n"(N) : "memory");
}
__device__ __forceinline__ void mma_f16(float* d, const uint32_t* a, const uint32_t* b) {
    asm volatile(
        "mma.sync.aligned.m16n8k16.row.col.f32.f16.f16.f32 "
        "{%0,%1,%2,%3}, {%4,%5,%6,%7}, {%8,%9}, {%0,%1,%2,%3};"
        : "+f"(d[0]), "+f"(d[1]), "+f"(d[2]), "+f"(d[3])
        : "r"(a[0]), "r"(a[1]), "r"(a[2]), "r"(a[3]), "r"(b[0]), "r"(b[1]));
}
__device__ __forceinline__ void bfly4(float& e0, float& e1, float& e2, float& e3) {
    float u0 = e0 + e1, u1 = e0 - e1, u2 = e2 + e3, u3 = e2 - e3;
    e0 = u0 + u2; e1 = u1 + u3; e2 = u0 - u2; e3 = u1 - u3;
}
// In-register H_16 (4 butterfly stages) on e[0..15]
__device__ __forceinline__ void h16(float* e) {
    bfly4(e[0], e[1], e[2], e[3]);   bfly4(e[4], e[5], e[6], e[7]);
    bfly4(e[8], e[9], e[10], e[11]); bfly4(e[12], e[13], e[14], e[15]);
    bfly4(e[0], e[4], e[8], e[12]);  bfly4(e[1], e[5], e[9], e[13]);
    bfly4(e[2], e[6], e[10], e[14]); bfly4(e[3], e[7], e[11], e[15]);
}

// FHT smem: layout A = i + (i>>4); layout B = i + (i>>8)*16. Max idx 4350.
#define FHT_SMEM 4352

// ---------------------------------------------------------------------------
// Kernel 1 (merged): blocks [0, BATCH): x_rht = fp16(FHT(x*SV)/64)
//                    blocks [BATCH, BATCH+NGRP/256): dequant W -> fp16
// ---------------------------------------------------------------------------
__global__ __launch_bounds__(256) void pre_kernel(
    const float* __restrict__ x, const float* __restrict__ SV,
    const int* __restrict__ Qidxs, const int* __restrict__ Qidxs2,
    const float* __restrict__ cb, const float* __restrict__ cb2,
    const float* __restrict__ irs_p)
{
    __shared__ float s[FHT_SMEM];
    const int t = threadIdx.x;

    if (blockIdx.x >= BATCH) {
        // ---- dequant path ----
        int g = (blockIdx.x - BATCH) * 256 + t;
        const float irs = __ldg(irs_p);
        const int q  = Qidxs[g];
        const int q2 = Qidxs2[g];

        float4 c0 = __ldg((const float4*)cb  + q  * 2);
        float4 c1 = __ldg((const float4*)cb  + q  * 2 + 1);
        float4 d0 = __ldg((const float4*)cb2 + q2 * 2);
        float4 d1 = __ldg((const float4*)cb2 + q2 * 2 + 1);

        __half2 h0 = __floats2half2_rn(fmaf(irs, d0.x, c0.x), fmaf(irs, d0.y, c0.y));
        __half2 h1 = __floats2half2_rn(fmaf(irs, d0.z, c0.z), fmaf(irs, d0.w, c0.w));
        __half2 h2 = __floats2half2_rn(fmaf(irs, d1.x, c1.x), fmaf(irs, d1.y, c1.y));
        __half2 h3 = __floats2half2_rn(fmaf(irs, d1.z, c1.z), fmaf(irs, d1.w, c1.w));

        uint4 u;
        u.x = *reinterpret_cast<uint32_t*>(&h0);
        u.y = *reinterpret_cast<uint32_t*>(&h1);
        u.z = *reinterpret_cast<uint32_t*>(&h2);
        u.w = *reinterpret_cast<uint32_t*>(&h3);
        *(uint4*)(g_W + (size_t)g * 8) = u;
        return;
    }

    // ---- FHT path ----
    const int row = blockIdx.x;
    float e[16];

    // Pass 1: stages h=1..8 on contiguous 16
    {
        const float* xr = x + (size_t)row * NDIM + t * 16;
        const float* sv = SV + t * 16;
#pragma unroll
        for (int q = 0; q < 4; q++) {
            float4 v = *(const float4*)(xr + 4 * q);
            float4 w = *(const float4*)(sv + 4 * q);
            e[4 * q + 0] = v.x * w.x; e[4 * q + 1] = v.y * w.y;
            e[4 * q + 2] = v.z * w.z; e[4 * q + 3] = v.w * w.w;
        }
        h16(e);
#pragma unroll
        for (int o = 0; o < 16; o++) s[17 * t + o] = e[o];   // layout A
    }
    __syncthreads();

    // Pass 2: stages h=16..128; i = b*256 + j*16 + r
    {
        const int r = t & 15, b = t >> 4;
        const int baseA = b * 272 + r;
#pragma unroll
        for (int j = 0; j < 16; j++) e[j] = s[baseA + j * 17];
        h16(e);
        __syncthreads();
        const int baseB = b * 272 + r;                       // layout B
#pragma unroll
        for (int j = 0; j < 16; j++) s[baseB + j * 16] = e[j];
    }
    __syncthreads();

    // Pass 3: stages h=256..2048; i = j*256 + t
    {
#pragma unroll
        for (int j = 0; j < 16; j++) e[j] = s[j * 272 + t];
        h16(e);
        const float sc = 0.015625f;
        __half* o = g_xrht + (size_t)row * NDIM;
#pragma unroll
        for (int j = 0; j < 16; j++) o[j * 256 + t] = __float2half_rn(e[j] * sc);
    }
}

// ---------------------------------------------------------------------------
// Kernel 2: fp16 mma.sync GEMM (scalar LDS fragment loads)
// CTA 128x128, 4 warps (2x2), warp tile 64x64, BKH=64, 3-stage cp.async.
// ---------------------------------------------------------------------------
__global__ __launch_bounds__(128, 2) void gemm_f16_kernel()
{
    extern __shared__ __half smh[];

    const int tid  = threadIdx.x;
    const int wid  = tid >> 5;
    const int lane = tid & 31;
    const int gid  = lane >> 2;
    const int tig  = lane & 3;
    const int wm   = (wid >> 1) * 64;
    const int wn   = (wid & 1) * 64;

    const int brow = blockIdx.y * CTA_M;
    const int bcol = blockIdx.x * CTA_N;

    const uint32_t sbase = smem_u32(smh);

    float acc[4][8][4];
#pragma unroll
    for (int i = 0; i < 4; i++)
#pragma unroll
        for (int j = 0; j < 8; j++)
#pragma unroll
            for (int q = 0; q < 4; q++) acc[i][j][q] = 0.0f;

    auto load_stage = [&](int st, int kc) {
        const int k0 = kc * BKH;
        const uint32_t bA = sbase + (uint32_t)st * STG_BYTES;
        const uint32_t bB = sbase + (uint32_t)(STAGES + st) * STG_BYTES;
#pragma unroll
        for (int s = 0; s < 8; s++) {
            int c = s * 128 + tid;
            int row = c >> 3, seg = c & 7;
            cp_async16(bA + row * (SROWH * 2) + seg * 16,
                       g_xrht + (size_t)(brow + row) * NDIM + k0 + seg * 8);
            cp_async16(bB + row * (SROWH * 2) + seg * 16,
                       g_W    + (size_t)(bcol + row) * NDIM + k0 + seg * 8);
        }
    };

#pragma unroll
    for (int s = 0; s < STAGES - 1; s++) {
        load_stage(s, s);
        cp_commit();
    }

    for (int kc = 0; kc < KCHUNKS; kc++) {
        cp_wait<STAGES - 2>();
        __syncthreads();

        if (kc + STAGES - 1 < KCHUNKS)
            load_stage((kc + STAGES - 1) % STAGES, kc + STAGES - 1);
        cp_commit();

        const int st = kc % STAGES;
        const __half* Ast = smh + (size_t)st * 128 * SROWH;
        const __half* Bst = smh + (size_t)(STAGES + st) * 128 * SROWH;

#pragma unroll
        for (int ks = 0; ks < 4; ks++) {
            const int k = ks * 16;
            uint32_t af[4][4], bf[8][2];
#pragma unroll
            for (int i = 0; i < 4; i++) {
                const __half* ap = Ast + (wm + i * 16 + gid) * SROWH + k + tig * 2;
                af[i][0] = *(const uint32_t*)(ap);
                af[i][1] = *(const uint32_t*)(ap + 8 * SROWH);
                af[i][2] = *(const uint32_t*)(ap + 8);
                af[i][3] = *(const uint32_t*)(ap + 8 * SROWH + 8);
            }
#pragma unroll
            for (int j = 0; j < 8; j++) {
                const __half* bp = Bst + (wn + j * 8 + gid) * SROWH + k + tig * 2;
                bf[j][0] = *(const uint32_t*)(bp);
                bf[j][1] = *(const uint32_t*)(bp + 8);
            }
#pragma unroll
            for (int i = 0; i < 4; i++)
#pragma unroll
                for (int j = 0; j < 8; j++)
                    mma_f16(acc[i][j], af[i], bf[j]);
        }
    }

    // epilogue: fp16 y_rht (c0 is even -> 4B-aligned half2 stores)
#pragma unroll
    for (int i = 0; i < 4; i++) {
        const int r0 = brow + wm + i * 16 + gid;
#pragma unroll
        for (int j = 0; j < 8; j++) {
            const int c0 = bcol + wn + j * 8 + tig * 2;
            __half2 lo = __floats2half2_rn(acc[i][j][0], acc[i][j][1]);
            __half2 hi = __floats2half2_rn(acc[i][j][2], acc[i][j][3]);
            *(__half2*)&g_yrht[(size_t)r0 * MDIM + c0] = lo;
            *(__half2*)&g_yrht[(size_t)(r0 + 8) * MDIM + c0] = hi;
        }
    }
}

// ---------------------------------------------------------------------------
// Kernel 3: y = FHT(y_rht) * SU * Wscale / 64 — 3-pass register FHT
// ---------------------------------------------------------------------------
__global__ __launch_bounds__(256) void fht_post_kernel(
    float* __restrict__ out, const float* __restrict__ SU,
    const float* __restrict__ wscale_p)
{
    __shared__ float s[FHT_SMEM];
    const int row = blockIdx.x;
    const int t = threadIdx.x;
    float e[16];

    {
        // 16 halves = 32 bytes = TWO uint4 loads (base + t*16 halves -> 32B offset, aligned)
        const __half* yr = g_yrht + (size_t)row * MDIM + t * 16;
        uint4 u0 = *(const uint4*)(yr);
        uint4 u1 = *(const uint4*)(yr + 8);
        const __half2* hp0 = (const __half2*)&u0;
        const __half2* hp1 = (const __half2*)&u1;
#pragma unroll
        for (int q = 0; q < 4; q++) {
            float2 f0 = __half22float2(hp0[q]);
            float2 f1 = __half22float2(hp1[q]);
            e[2 * q]     = f0.x; e[2 * q + 1]     = f0.y;
            e[8 + 2 * q] = f1.x; e[8 + 2 * q + 1] = f1.y;
        }
        h16(e);
#pragma unroll
        for (int o = 0; o < 16; o++) s[17 * t + o] = e[o];
    }
    __syncthreads();

    {
        const int r = t & 15, b = t >> 4;
        const int baseA = b * 272 + r;
#pragma unroll
        for (int j = 0; j < 16; j++) e[j] = s[baseA + j * 17];
        h16(e);
        __syncthreads();
        const int baseB = b * 272 + r;
#pragma unroll
        for (int j = 0; j < 16; j++) s[baseB + j * 16] = e[j];
    }
    __syncthreads();

    {
#pragma unroll
        for (int j = 0; j < 16; j++) e[j] = s[j * 272 + t];
        h16(e);
        const float ws = __ldg(wscale_p) * 0.015625f;
        float* o = out + (size_t)row * MDIM;
#pragma unroll
        for (int j = 0; j < 16; j++)
            o[j * 256 + t] = e[j] * SU[j * 256 + t] * ws;
    }
}

// ---------------------------------------------------------------------------
// Launch
// ---------------------------------------------------------------------------
extern "C" void kernel_launch(void* const* d_in, const int* in_sizes, int n_in,
                              void* d_out, int out_size)
{
    const float* x      = (const float*)d_in[0];
    const int*   Qidxs  = (const int*)  d_in[1];
    const int*   Qidxs2 = (const int*)  d_in[2];
    const float* SU     = (const float*)d_in[3];
    const float* SV     = (const float*)d_in[4];
    const float* cb     = (const float*)d_in[5];
    const float* cb2    = (const float*)d_in[6];
    const float* Wscale = (const float*)d_in[7];
    const float* irs    = (const float*)d_in[8];
    float* out = (float*)d_out;
    (void)in_sizes; (void)n_in; (void)out_size;

    cudaFuncSetAttribute(gemm_f16_kernel,
                         cudaFuncAttributeMaxDynamicSharedMemorySize, DYN_SMEM);

    // FHT-pre (blocks 0..8191) + dequant (blocks 8192..16383) in one launch
    pre_kernel<<<BATCH + NGRP / 256, 256>>>(x, SV, Qidxs, Qidxs2, cb, cb2, irs);

    dim3 grid(MDIM / CTA_N, BATCH / CTA_M);
    gemm_f16_kernel<<<grid, 128, DYN_SMEM>>>();

    fht_post_kernel<<<BATCH, 256>>>(out, SU, Wscale);
}

// round 16
// speedup vs baseline: 7.8676x; 1.0639x over previous
#include <cuda_runtime.h>
#include <cuda_fp16.h>
#include <cstdint>

// ---------------------------------------------------------------------------
// Problem dims (fixed by the dataset)
// ---------------------------------------------------------------------------
#define BATCH 8192
#define NDIM  4096
#define MDIM  4096
#define NGRP  (MDIM * 512)

// GEMM tiling (fp16 operands, fp32 accum)
#define CTA_M 128
#define CTA_N 128
#define BKH   64
#define KCHUNKS (NDIM / BKH)        // 64
#define STAGES 2
#define SROWH 72                    // padded row stride in halves
#define STG_BYTES (128 * SROWH * 2) // 18432 B
#define DYN_SMEM (2 * STAGES * STG_BYTES)   // 73728 B -> 3 CTAs/SM

// ---------------------------------------------------------------------------
// Scratch (16B-aligned: vector/cp.async access everywhere)
// ---------------------------------------------------------------------------
__device__ __align__(16) __half g_xrht[(size_t)BATCH * NDIM];  // 64 MB
__device__ __align__(16) __half g_W   [(size_t)MDIM  * NDIM];  // 32 MB
__device__ __align__(16) __half g_yrht[(size_t)BATCH * MDIM];  // 64 MB (fp16)

// ---------------------------------------------------------------------------
// Helpers
// ---------------------------------------------------------------------------
__device__ __forceinline__ uint32_t smem_u32(const void* p) {
    uint32_t a;
    asm("{ .reg .u64 t; cvta.to.shared.u64 t, %1; cvt.u32.u64 %0, t; }" : "=r"(a) : "l"(p));
    return a;
}
__device__ __forceinline__ void cp_async16(uint32_t dst, const void* src) {
    asm volatile("cp.async.cg.shared.global [%0], [%1], 16;" :: "r"(dst), "l"(src));
}
__device__ __forceinline__ void cp_commit() {
    asm volatile("cp.async.commit_group;" ::: "memory");
}
template <int N>
__device__ __forceinline__ void cp_wait() {
    asm volatile("cp.async.wait_group %0;" :: "n"(N) : "memory");
}
__device__ __forceinline__ void mma_f16(float* d, const uint32_t* a, const uint32_t* b) {
    asm volatile(
        "mma.sync.aligned.m16n8k16.row.col.f32.f16.f16.f32 "
        "{%0,%1,%2,%3}, {%4,%5,%6,%7}, {%8,%9}, {%0,%1,%2,%3};"
        : "+f"(d[0]), "+f"(d[1]), "+f"(d[2]), "+f"(d[3])
        : "r"(a[0]), "r"(a[1]), "r"(a[2]), "r"(a[3]), "r"(b[0]), "r"(b[1]));
}
__device__ __forceinline__ void bfly4(float& e0, float& e1, float& e2, float& e3) {
    float u0 = e0 + e1, u1 = e0 - e1, u2 = e2 + e3, u3 = e2 - e3;
    e0 = u0 + u2; e1 = u1 + u3; e2 = u0 - u2; e3 = u1 - u3;
}
// In-register H_16 (4 butterfly stages) on e[0..15]
__device__ __forceinline__ void h16(float* e) {
    bfly4(e[0], e[1], e[2], e[3]);   bfly4(e[4], e[5], e[6], e[7]);
    bfly4(e[8], e[9], e[10], e[11]); bfly4(e[12], e[13], e[14], e[15]);
    bfly4(e[0], e[4], e[8], e[12]);  bfly4(e[1], e[5], e[9], e[13]);
    bfly4(e[2], e[6], e[10], e[14]); bfly4(e[3], e[7], e[11], e[15]);
}

// FHT smem: layout A = i + (i>>4); layout B = i + (i>>8)*16. Max idx 4350.
#define FHT_SMEM 4352

// ---------------------------------------------------------------------------
// Kernel 1: x_rht = fp16(FHT(x*SV)/64) — 3 passes, 16 elems/thread in regs
// ---------------------------------------------------------------------------
__global__ __launch_bounds__(256) void fht_pre_kernel(
    const float* __restrict__ x, const float* __restrict__ SV)
{
    __shared__ float s[FHT_SMEM];
    const int row = blockIdx.x;
    const int t = threadIdx.x;
    float e[16];

    // Pass 1: stages h=1..8 on contiguous 16
    {
        const float* xr = x + (size_t)row * NDIM + t * 16;
        const float* sv = SV + t * 16;
#pragma unroll
        for (int q = 0; q < 4; q++) {
            float4 v = *(const float4*)(xr + 4 * q);
            float4 w = *(const float4*)(sv + 4 * q);
            e[4 * q + 0] = v.x * w.x; e[4 * q + 1] = v.y * w.y;
            e[4 * q + 2] = v.z * w.z; e[4 * q + 3] = v.w * w.w;
        }
        h16(e);
#pragma unroll
        for (int o = 0; o < 16; o++) s[17 * t + o] = e[o];   // layout A
    }
    __syncthreads();

    // Pass 2: stages h=16..128; i = b*256 + j*16 + r
    {
        const int r = t & 15, b = t >> 4;
        const int baseA = b * 272 + r;
#pragma unroll
        for (int j = 0; j < 16; j++) e[j] = s[baseA + j * 17];
        h16(e);
        __syncthreads();
        const int baseB = b * 272 + r;                       // layout B
#pragma unroll
        for (int j = 0; j < 16; j++) s[baseB + j * 16] = e[j];
    }
    __syncthreads();

    // Pass 3: stages h=256..2048; i = j*256 + t
    {
#pragma unroll
        for (int j = 0; j < 16; j++) e[j] = s[j * 272 + t];
        h16(e);
        const float sc = 0.015625f;
        __half* o = g_xrht + (size_t)row * NDIM;
#pragma unroll
        for (int j = 0; j < 16; j++) o[j * 256 + t] = __float2half_rn(e[j] * sc);
    }
}

// ---------------------------------------------------------------------------
// Kernel 2: dequantize W -> fp16
// ---------------------------------------------------------------------------
__global__ __launch_bounds__(256) void dequant_kernel(
    const int* __restrict__ Qidxs, const int* __restrict__ Qidxs2,
    const float* __restrict__ cb, const float* __restrict__ cb2,
    const float* __restrict__ irs_p)
{
    int g = blockIdx.x * blockDim.x + threadIdx.x;
    if (g >= NGRP) return;
    const float irs = __ldg(irs_p);
    const int q  = Qidxs[g];
    const int q2 = Qidxs2[g];

    float4 c0 = __ldg((const float4*)cb  + q  * 2);
    float4 c1 = __ldg((const float4*)cb  + q  * 2 + 1);
    float4 d0 = __ldg((const float4*)cb2 + q2 * 2);
    float4 d1 = __ldg((const float4*)cb2 + q2 * 2 + 1);

    __half2 h0 = __floats2half2_rn(fmaf(irs, d0.x, c0.x), fmaf(irs, d0.y, c0.y));
    __half2 h1 = __floats2half2_rn(fmaf(irs, d0.z, c0.z), fmaf(irs, d0.w, c0.w));
    __half2 h2 = __floats2half2_rn(fmaf(irs, d1.x, c1.x), fmaf(irs, d1.y, c1.y));
    __half2 h3 = __floats2half2_rn(fmaf(irs, d1.z, c1.z), fmaf(irs, d1.w, c1.w));

    uint4 u;
    u.x = *reinterpret_cast<uint32_t*>(&h0);
    u.y = *reinterpret_cast<uint32_t*>(&h1);
    u.z = *reinterpret_cast<uint32_t*>(&h2);
    u.w = *reinterpret_cast<uint32_t*>(&h3);
    *(uint4*)(g_W + (size_t)g * 8) = u;
}

// ---------------------------------------------------------------------------
// Kernel 3: fp16 mma.sync GEMM (scalar LDS fragment loads)
// CTA 128x128, 4 warps (2x2), warp tile 64x64, BKH=64, 2-stage cp.async,
// 3 CTAs/SM (12 warps) for tensor-pipe saturation.
// ---------------------------------------------------------------------------
__global__ __launch_bounds__(128, 3) void gemm_f16_kernel()
{
    extern __shared__ __half smh[];

    const int tid  = threadIdx.x;
    const int wid  = tid >> 5;
    const int lane = tid & 31;
    const int gid  = lane >> 2;
    const int tig  = lane & 3;
    const int wm   = (wid >> 1) * 64;
    const int wn   = (wid & 1) * 64;

    const int brow = blockIdx.y * CTA_M;
    const int bcol = blockIdx.x * CTA_N;

    const uint32_t sbase = smem_u32(smh);

    float acc[4][8][4];
#pragma unroll
    for (int i = 0; i < 4; i++)
#pragma unroll
        for (int j = 0; j < 8; j++)
#pragma unroll
            for (int q = 0; q < 4; q++) acc[i][j][q] = 0.0f;

    auto load_stage = [&](int st, int kc) {
        const int k0 = kc * BKH;
        const uint32_t bA = sbase + (uint32_t)st * STG_BYTES;
        const uint32_t bB = sbase + (uint32_t)(STAGES + st) * STG_BYTES;
#pragma unroll
        for (int s = 0; s < 8; s++) {
            int c = s * 128 + tid;
            int row = c >> 3, seg = c & 7;
            cp_async16(bA + row * (SROWH * 2) + seg * 16,
                       g_xrht + (size_t)(brow + row) * NDIM + k0 + seg * 8);
            cp_async16(bB + row * (SROWH * 2) + seg * 16,
                       g_W    + (size_t)(bcol + row) * NDIM + k0 + seg * 8);
        }
    };

    // prologue: stage 0
    load_stage(0, 0);
    cp_commit();

    for (int kc = 0; kc < KCHUNKS; kc++) {
        cp_wait<0>();          // only kc's group is pending here
        __syncthreads();       // all warps done with the buffer we're about to refill

        if (kc + 1 < KCHUNKS)
            load_stage((kc + 1) & 1, kc + 1);
        cp_commit();

        const int st = kc & 1;
        const __half* Ast = smh + (size_t)st * 128 * SROWH;
        const __half* Bst = smh + (size_t)(STAGES + st) * 128 * SROWH;

#pragma unroll
        for (int ks = 0; ks < 4; ks++) {
            const int k = ks * 16;
            uint32_t af[4][4], bf[8][2];
#pragma unroll
            for (int i = 0; i < 4; i++) {
                const __half* ap = Ast + (wm + i * 16 + gid) * SROWH + k + tig * 2;
                af[i][0] = *(const uint32_t*)(ap);
                af[i][1] = *(const uint32_t*)(ap + 8 * SROWH);
                af[i][2] = *(const uint32_t*)(ap + 8);
                af[i][3] = *(const uint32_t*)(ap + 8 * SROWH + 8);
            }
#pragma unroll
            for (int j = 0; j < 8; j++) {
                const __half* bp = Bst + (wn + j * 8 + gid) * SROWH + k + tig * 2;
                bf[j][0] = *(const uint32_t*)(bp);
                bf[j][1] = *(const uint32_t*)(bp + 8);
            }
#pragma unroll
            for (int i = 0; i < 4; i++)
#pragma unroll
                for (int j = 0; j < 8; j++)
                    mma_f16(acc[i][j], af[i], bf[j]);
        }
    }

    // epilogue: fp16 y_rht (c0 even -> 4B-aligned half2 stores)
#pragma unroll
    for (int i = 0; i < 4; i++) {
        const int r0 = brow + wm + i * 16 + gid;
#pragma unroll
        for (int j = 0; j < 8; j++) {
            const int c0 = bcol + wn + j * 8 + tig * 2;
            __half2 lo = __floats2half2_rn(acc[i][j][0], acc[i][j][1]);
            __half2 hi = __floats2half2_rn(acc[i][j][2], acc[i][j][3]);
            *(__half2*)&g_yrht[(size_t)r0 * MDIM + c0] = lo;
            *(__half2*)&g_yrht[(size_t)(r0 + 8) * MDIM + c0] = hi;
        }
    }
}

// ---------------------------------------------------------------------------
// Kernel 4: y = FHT(y_rht) * SU * Wscale / 64 — 3-pass register FHT
// ---------------------------------------------------------------------------
__global__ __launch_bounds__(256) void fht_post_kernel(
    float* __restrict__ out, const float* __restrict__ SU,
    const float* __restrict__ wscale_p)
{
    __shared__ float s[FHT_SMEM];
    const int row = blockIdx.x;
    const int t = threadIdx.x;
    float e[16];

    {
        // 16 halves = 32 bytes = TWO uint4 loads
        const __half* yr = g_yrht + (size_t)row * MDIM + t * 16;
        uint4 u0 = *(const uint4*)(yr);
        uint4 u1 = *(const uint4*)(yr + 8);
        const __half2* hp0 = (const __half2*)&u0;
        const __half2* hp1 = (const __half2*)&u1;
#pragma unroll
        for (int q = 0; q < 4; q++) {
            float2 f0 = __half22float2(hp0[q]);
            float2 f1 = __half22float2(hp1[q]);
            e[2 * q]     = f0.x; e[2 * q + 1]     = f0.y;
            e[8 + 2 * q] = f1.x; e[8 + 2 * q + 1] = f1.y;
        }
        h16(e);
#pragma unroll
        for (int o = 0; o < 16; o++) s[17 * t + o] = e[o];
    }
    __syncthreads();

    {
        const int r = t & 15, b = t >> 4;
        const int baseA = b * 272 + r;
#pragma unroll
        for (int j = 0; j < 16; j++) e[j] = s[baseA + j * 17];
        h16(e);
        __syncthreads();
        const int baseB = b * 272 + r;
#pragma unroll
        for (int j = 0; j < 16; j++) s[baseB + j * 16] = e[j];
    }
    __syncthreads();

    {
#pragma unroll
        for (int j = 0; j < 16; j++) e[j] = s[j * 272 + t];
        h16(e);
        const float ws = __ldg(wscale_p) * 0.015625f;
        float* o = out + (size_t)row * MDIM;
#pragma unroll
        for (int j = 0; j < 16; j++)
            o[j * 256 + t] = e[j] * SU[j * 256 + t] * ws;
    }
}

// ---------------------------------------------------------------------------
// Launch
// ---------------------------------------------------------------------------
extern "C" void kernel_launch(void* const* d_in, const int* in_sizes, int n_in,
                              void* d_out, int out_size)
{
    const float* x      = (const float*)d_in[0];
    const int*   Qidxs  = (const int*)  d_in[1];
    const int*   Qidxs2 = (const int*)  d_in[2];
    const float* SU     = (const float*)d_in[3];
    const float* SV     = (const float*)d_in[4];
    const float* cb     = (const float*)d_in[5];
    const float* cb2    = (const float*)d_in[6];
    const float* Wscale = (const float*)d_in[7];
    const float* irs    = (const float*)d_in[8];
    float* out = (float*)d_out;
    (void)in_sizes; (void)n_in; (void)out_size;

    cudaFuncSetAttribute(gemm_f16_kernel,
                         cudaFuncAttributeMaxDynamicSharedMemorySize, DYN_SMEM);

    fht_pre_kernel<<<BATCH, 256>>>(x, SV);
    dequant_kernel<<<NGRP / 256, 256>>>(Qidxs, Qidxs2, cb, cb2, irs);

    dim3 grid(MDIM / CTA_N, BATCH / CTA_M);
    gemm_f16_kernel<<<grid, 128, DYN_SMEM>>>();

    fht_post_kernel<<<BATCH, 256>>>(out, SU, Wscale);
}